// round 15
// baseline (speedup 1.0000x reference)
#include <cuda_runtime.h>
#include <cuda_fp16.h>
#include <cstdint>

#define BB 32768
#define DD 512
#define EE 10
#define HH 128
#define RH1 256
#define RH2 128

// ---- packed fp16 scratch (static __device__ globals: allocation-guard safe) ----
// A-side arrays: [row][kp] (kp contiguous), u32 = half2(v[2k], v[2k+1]).
// B-side (weight) arrays: [n][kp] (kp contiguous) -> ldmatrix-ready.
__device__ uint32_t g_xtp[(size_t)BB * (DD / 2)];        // x packed    [B][256]
__device__ uint32_t g_hr1p[(size_t)BB * (RH1 / 2)];      // hr1 packed  [B][128]
__device__ uint32_t g_w1p[(size_t)RH1 * (DD / 2)];       // rw1 packed  [256 n][256 kp]
__device__ uint32_t g_w2p[(size_t)RH2 * (RH1 / 2)];      // rw2 packed  [128 n][128 kp]
__device__ uint32_t g_e1p[(size_t)EE * HH * (DD / 2)];   // we1 packed  [10][128 n][256 kp]
__device__ uint32_t g_e2p[(size_t)EE * HH * (HH / 2)];   // we2 packed  [10][128 n][64 kp]
__device__ int      g_cnt[BB / 128];                     // completion counters

__device__ __forceinline__ uint32_t pkh2(float a, float b) {
    __half2 h = __floats2half2_rn(a, b);
    return *reinterpret_cast<uint32_t*>(&h);
}
__device__ __forceinline__ uint32_t s2u(const void* p) {
    uint32_t a;
    asm("{ .reg .u64 t; cvta.to.shared.u64 t, %1; cvt.u32.u64 %0, t; }" : "=r"(a) : "l"(p));
    return a;
}
__device__ __forceinline__ void ldsm4(uint32_t& r0, uint32_t& r1, uint32_t& r2,
                                      uint32_t& r3, uint32_t a) {
    asm volatile("ldmatrix.sync.aligned.m8n8.x4.shared.b16 {%0,%1,%2,%3}, [%4];"
                 : "=r"(r0), "=r"(r1), "=r"(r2), "=r"(r3) : "r"(a));
}

// ---- smem geometry (u32 units). Strides mod 32 = 4 -> conflict-free.
#define A_STRIDE 36                        // 128 rows x 32 kp u32, stride 36
#define A_STG (128 * A_STRIDE)             // 4608 u32 (A chunk tile)
#define B_STG (128 * A_STRIDE)             // 4608 u32 (B chunk tile, same shape)
#define STG_F (A_STG + B_STG)              // 9216 u32 per stage
#define AUX_OFF (2 * STG_F)                // expert L2-B double buffer (2 x B_STG)
#define H1_STRIDE 68                       // h1 packed buffer: 128 rows x 64 kp u32
#define MEGA_SMEM ((AUX_OFF + 2 * B_STG) * 4)   // 110592 B -> 2 CTAs/SM

#define CPA(dst, src) \
    asm volatile("cp.async.cg.shared.global [%0], [%1], 16;" :: "r"(dst), "l"(src) : "memory")
#define CPC() asm volatile("cp.async.commit_group;" ::: "memory")
#define CPW0() asm volatile("cp.async.wait_group 0;" ::: "memory")

#define MMA16(cc, a0, a1, a2, a3, b0, b1) \
    asm volatile("mma.sync.aligned.m16n8k16.row.col.f32.f16.f16.f32 " \
                 "{%0,%1,%2,%3}, {%4,%5,%6,%7}, {%8,%9}, {%0,%1,%2,%3};" \
                 : "+f"(cc[0]), "+f"(cc[1]), "+f"(cc[2]), "+f"(cc[3]) \
                 : "r"(a0), "r"(a1), "r"(a2), "r"(a3), "r"(b0), "r"(b1))

// One 64-k chunk (4 x k16 steps) of 128x128 CTA-tile MMA via ldmatrix.
// aAddr/bAddr: per-lane tile base addresses (see lane-offset derivation at
// call site). AST = A row stride in BYTES (144 main tiles, 272 h1 buffer).
// B row stride fixed 144.
template <int AST>
__device__ __forceinline__ void mma_chunk(uint32_t aAddr, uint32_t bAddr,
                                          float (&c)[2][8][4])
{
#pragma unroll
    for (int s = 0; s < 4; s++) {
        uint32_t a[2][4];
#pragma unroll
        for (int mt = 0; mt < 2; mt++)
            ldsm4(a[mt][0], a[mt][1], a[mt][2], a[mt][3],
                  aAddr + mt * 16 * AST + s * 32);
        uint32_t b[8][2];
#pragma unroll
        for (int np = 0; np < 4; np++)
            ldsm4(b[2 * np][0], b[2 * np][1], b[2 * np + 1][0], b[2 * np + 1][1],
                  bAddr + np * 16 * 144 + s * 32);
#pragma unroll
        for (int mt = 0; mt < 2; mt++)
#pragma unroll
            for (int nt = 0; nt < 8; nt++)
                MMA16(c[mt][nt], a[mt][0], a[mt][1], a[mt][2], a[mt][3],
                      b[nt][0], b[nt][1]);
    }
}

// ============================================================================
// Megakernel (R13 structure, ldmatrix fragments). grid = (256 row-blocks,
// 3 roles), 256 threads, 2 CTAs/SM, 2-stage cp.async ring with CPW0.
//   y=0: experts 0..4 -> chart    y=1: experts 5..9 -> chart
//   y=2: router L1 (2 col tiles) + L2 + logits + gumbel -> wts
// 3rd finisher per row-block computes z.
// ============================================================================
__global__ __launch_bounds__(256, 2) void mega(
    const uint32_t* __restrict__ xtp, const uint32_t* __restrict__ w1p,
    const float* __restrict__ rb1, const uint32_t* __restrict__ w2p,
    const float* __restrict__ rb2, const float* __restrict__ rw3,
    const float* __restrict__ rb3, const float* __restrict__ u,
    const uint32_t* __restrict__ e1p, const float* __restrict__ eb1,
    const uint32_t* __restrict__ e2p, const float* __restrict__ eb2,
    const float* __restrict__ ew3, const float* __restrict__ eb3,
    uint32_t* __restrict__ hr1p, float* __restrict__ wts,
    float* __restrict__ chart, float* __restrict__ z)
{
    extern __shared__ uint32_t smu[];
    __shared__ float zcs[256];
    __shared__ float ew3s[256];
    __shared__ float eb1s[128];
    __shared__ float eb2s[128];
    __shared__ int s_old;

    const uint32_t smem_base = s2u(smu);
    const int tid = threadIdx.x;
    const int wid = tid >> 5, lane = tid & 31;
    const int grp = lane >> 2, tig = lane & 3;
    const int warp_m = wid & 3, warp_n = wid >> 2;   // 4 x 2 warps, 32x64 tiles
    const int row0 = blockIdx.x * 128;
    const int role = (blockIdx.y == 2) ? 0 : (int)blockIdx.y + 1;  // experts first

    // ldmatrix per-lane tile offsets. t8 = lane>>3 selects the x4 sub-tile:
    //   A: t&1 -> +8 rows (a1/a3), t>>1 -> +4 kp (a2/a3)
    //   B: t>>1 -> +8 n rows (next nt), t&1 -> +4 kp (b1)
    const int t8 = lane >> 3, r8 = lane & 7;
    const uint32_t aLane144 = (uint32_t)((warp_m * 32 + (t8 & 1) * 8 + r8) * 144
                                         + (t8 >> 1) * 16);
    const uint32_t aLane272 = (uint32_t)((warp_m * 32 + (t8 & 1) * 8 + r8) * 272
                                         + (t8 >> 1) * 16);
    const uint32_t bLane144 = (uint32_t)((warp_n * 64 + (t8 >> 1) * 8 + r8) * 144
                                         + (t8 & 1) * 16);

    // cp.async staging map (A and B tiles identical shape: 128 rows x 128B)
    const int arow = tid >> 1, ahalf = tid & 1;     // row, 4 x 16B per thread

    float c[2][8][4];

    if (role == 0) {
        // ---------------- ROUTER ----------------
        const uint32_t* Ag = xtp + (long long)(row0 + arow) * (DD / 2);

        // --- R1: two 128-col tiles, K=512 -> 8 chunks of 64k ---
        for (int ct = 0; ct < 2; ct++) {
            const uint32_t* Bg = w1p + (long long)(ct * 128 + arow) * (DD / 2);
            auto loadR1 = [&](int i) {
                const uint32_t sA = smem_base + (i & 1) * (STG_F * 4);
                const uint32_t sB = sA + A_STG * 4;
#pragma unroll
                for (int j = 0; j < 4; j++) {
                    const int k4 = ahalf * 4 + j;
                    CPA(sA + arow * 144 + k4 * 16, Ag + i * 32 + k4 * 4);
                    CPA(sB + arow * 144 + k4 * 16, Bg + i * 32 + k4 * 4);
                }
                CPC();
            };
#pragma unroll
            for (int mt = 0; mt < 2; mt++)
#pragma unroll
                for (int nt = 0; nt < 8; nt++)
#pragma unroll
                    for (int q = 0; q < 4; q++) c[mt][nt][q] = 0.f;

            loadR1(0);
            for (int i = 0; i < 8; i++) {
                CPW0();
                __syncthreads();
                if (i + 1 < 8) loadR1(i + 1);
                const uint32_t sA = smem_base + (i & 1) * (STG_F * 4);
                mma_chunk<144>(sA + aLane144, sA + A_STG * 4 + bLane144, c);
            }

            // epilogue: hr1p[:, ct half] = pack(relu(c + rb1))
#pragma unroll
            for (int mt = 0; mt < 2; mt++) {
                const int rb = row0 + warp_m * 32 + mt * 16 + grp;
#pragma unroll
                for (int nt = 0; nt < 8; nt++) {
                    const int col = warp_n * 64 + nt * 8 + 2 * tig;   // 0..127 in ct
                    const int colp = ct * 64 + (col >> 1);
                    const float b0 = rb1[ct * 128 + col], b1 = rb1[ct * 128 + col + 1];
                    const float v0 = fmaxf(c[mt][nt][0] + b0, 0.f);
                    const float v1 = fmaxf(c[mt][nt][1] + b1, 0.f);
                    const float v2 = fmaxf(c[mt][nt][2] + b0, 0.f);
                    const float v3 = fmaxf(c[mt][nt][3] + b1, 0.f);
                    hr1p[(long long)rb * (RH1 / 2) + colp]       = pkh2(v0, v1);
                    hr1p[(long long)(rb + 8) * (RH1 / 2) + colp] = pkh2(v2, v3);
                }
            }
            __syncthreads();   // ring drained before next ct / R2
        }

        // --- R2: K=256 -> 4 chunks, A = hr1p rows ---
        const uint32_t* Ag2 = hr1p + (long long)(row0 + arow) * (RH1 / 2);
        const uint32_t* Bg2 = w2p + (long long)arow * (RH1 / 2);
        auto loadR2 = [&](int i) {
            const uint32_t sA = smem_base + (i & 1) * (STG_F * 4);
            const uint32_t sB = sA + A_STG * 4;
#pragma unroll
            for (int j = 0; j < 4; j++) {
                const int k4 = ahalf * 4 + j;
                CPA(sA + arow * 144 + k4 * 16, Ag2 + i * 32 + k4 * 4);
                CPA(sB + arow * 144 + k4 * 16, Bg2 + i * 32 + k4 * 4);
            }
            CPC();
        };
#pragma unroll
        for (int mt = 0; mt < 2; mt++)
#pragma unroll
            for (int nt = 0; nt < 8; nt++)
#pragma unroll
                for (int q = 0; q < 4; q++) c[mt][nt][q] = 0.f;

        loadR2(0);
        for (int i = 0; i < 4; i++) {
            CPW0();
            __syncthreads();
            if (i + 1 < 4) loadR2(i + 1);
            const uint32_t sA = smem_base + (i & 1) * (STG_F * 4);
            mma_chunk<144>(sA + aLane144, sA + A_STG * 4 + bLane144, c);
        }
        __syncthreads();   // ring drained; overlay w3s/lgs there

        // --- logits: relu(c + rb2) @ rw3, smem atomics ---
        float* w3s = (float*)smu;                   // [RH2][EE]
        float* lgs = (float*)smu + RH2 * EE;        // [128][EE]
        for (int i = tid; i < RH2 * EE; i += 256) { w3s[i] = rw3[i]; lgs[i] = 0.f; }
        __syncthreads();

#pragma unroll
        for (int mt = 0; mt < 2; mt++) {
            float pl0[EE], pl1[EE];
#pragma unroll
            for (int e = 0; e < EE; e++) { pl0[e] = 0.f; pl1[e] = 0.f; }
#pragma unroll
            for (int nt = 0; nt < 8; nt++) {
                const int col = warp_n * 64 + nt * 8 + 2 * tig;
                const float b0 = rb2[col], b1 = rb2[col + 1];
                const float v0 = fmaxf(c[mt][nt][0] + b0, 0.f);
                const float v1 = fmaxf(c[mt][nt][1] + b1, 0.f);
                const float v2 = fmaxf(c[mt][nt][2] + b0, 0.f);
                const float v3 = fmaxf(c[mt][nt][3] + b1, 0.f);
#pragma unroll
                for (int e = 0; e < EE; e++) {
                    const float w0 = w3s[col * EE + e], w1 = w3s[(col + 1) * EE + e];
                    pl0[e] += v0 * w0 + v1 * w1;
                    pl1[e] += v2 * w0 + v3 * w1;
                }
            }
            const int r = warp_m * 32 + mt * 16 + grp;
#pragma unroll
            for (int e = 0; e < EE; e++) {
                atomicAdd(&lgs[r * EE + e], pl0[e]);
                atomicAdd(&lgs[(r + 8) * EE + e], pl1[e]);
            }
        }
        __syncthreads();

        // --- gumbel softmax -> wts ---
        if (tid < 128) {
            const long long row = row0 + tid;
            float lg[EE];
            float m = -1e30f;
#pragma unroll
            for (int e = 0; e < EE; e++) {
                float uu = u[row * EE + e];
                uu = fminf(fmaxf(uu, 1e-10f), 1.0f);
                const float g = -logf(-logf(uu) + 1e-10f);
                lg[e] = (lgs[tid * EE + e] + rb3[e] + g) * (1.0f / 3.0f);
                m = fmaxf(m, lg[e]);
            }
            float s = 0.f;
#pragma unroll
            for (int e = 0; e < EE; e++) { lg[e] = expf(lg[e] - m); s += lg[e]; }
            const float inv = 1.0f / s;
#pragma unroll
            for (int e = 0; e < EE; e++) wts[row * EE + e] = lg[e] * inv;
        }
    } else {
        // ---------------- EXPERTS (5 per block) ----------------
        const int e0 = 5 * (role - 1);
        const uint32_t* Ag = xtp + (long long)(row0 + arow) * (DD / 2);

        auto loadL1 = [&](int e, int i) {
            const uint32_t sA = smem_base + (i & 1) * (STG_F * 4);
            const uint32_t sB = sA + A_STG * 4;
            const uint32_t* Bg = e1p + ((long long)e * HH + arow) * (DD / 2);
#pragma unroll
            for (int j = 0; j < 4; j++) {
                const int k4 = ahalf * 4 + j;
                CPA(sA + arow * 144 + k4 * 16, Ag + i * 32 + k4 * 4);
                CPA(sB + arow * 144 + k4 * 16, Bg + i * 32 + k4 * 4);
            }
            CPC();
        };
        auto loadL2B = [&](int e, int kc) {
            const uint32_t sB = smem_base + AUX_OFF * 4 + (kc & 1) * (B_STG * 4);
            const uint32_t* Bg = e2p + ((long long)e * HH + arow) * (HH / 2) + kc * 32;
#pragma unroll
            for (int j = 0; j < 4; j++) {
                const int k4 = ahalf * 4 + j;
                CPA(sB + arow * 144 + k4 * 16, Bg + k4 * 4);
            }
            CPC();
        };

        loadL1(e0, 0);
        for (int e = e0; e < e0 + 5; e++) {
            if (tid < 128) eb1s[tid] = eb1[e * HH + tid];
#pragma unroll
            for (int mt = 0; mt < 2; mt++)
#pragma unroll
                for (int nt = 0; nt < 8; nt++)
#pragma unroll
                    for (int q = 0; q < 4; q++) c[mt][nt][q] = 0.f;

            // --- L1: K=512 -> 8 chunks of 64k ---
            for (int i = 0; i < 8; i++) {
                CPW0();
                __syncthreads();
                if (i + 1 < 8) loadL1(e, i + 1);
                const uint32_t sA = smem_base + (i & 1) * (STG_F * 4);
                mma_chunk<144>(sA + aLane144, sA + A_STG * 4 + bLane144, c);
            }
            loadL2B(e, 0);      // AUX region: disjoint, safe to start now

            // --- h1 packed -> smem (128 x 68 u32, fits in stage 0; stage 0
            //     last read at chunk 6, globally synced at i=7 barrier) ---
#pragma unroll
            for (int mt = 0; mt < 2; mt++) {
                const int r = warp_m * 32 + mt * 16 + grp;
#pragma unroll
                for (int nt = 0; nt < 8; nt++) {
                    const int col = warp_n * 64 + nt * 8 + 2 * tig;
                    const int colp = col >> 1;
                    const float b0 = eb1s[col], b1 = eb1s[col + 1];
                    const float v0 = fmaxf(c[mt][nt][0] + b0, 0.f);
                    const float v1 = fmaxf(c[mt][nt][1] + b1, 0.f);
                    const float v2 = fmaxf(c[mt][nt][2] + b0, 0.f);
                    const float v3 = fmaxf(c[mt][nt][3] + b1, 0.f);
                    smu[r * H1_STRIDE + colp]       = pkh2(v0, v1);
                    smu[(r + 8) * H1_STRIDE + colp] = pkh2(v2, v3);
                }
            }

            // --- L2: K=128 -> 2 chunks, A from h1 smem, B double-buffered ---
#pragma unroll
            for (int mt = 0; mt < 2; mt++)
#pragma unroll
                for (int nt = 0; nt < 8; nt++)
#pragma unroll
                    for (int q = 0; q < 4; q++) c[mt][nt][q] = 0.f;

            for (int kc = 0; kc < 2; kc++) {
                CPW0();
                __syncthreads();    // kc=0: orders h1 writes before reads
                if (kc + 1 < 2) loadL2B(e, kc + 1);
                mma_chunk<272>(smem_base + aLane272 + kc * 128,
                               smem_base + AUX_OFF * 4 + (kc & 1) * (B_STG * 4)
                                   + bLane144, c);
            }
            __syncthreads();        // h1 reads done before stage-0 reuse

            if (e + 1 < e0 + 5) loadL1(e + 1, 0);

            // --- L3: zc = relu(c + eb2) @ ew3[e] -> chart ---
            ew3s[tid] = ew3[(long long)e * 256 + tid];
            if (tid < 128) eb2s[tid] = eb2[e * HH + tid];
            zcs[tid] = 0.f;
            __syncthreads();

#pragma unroll
            for (int mt = 0; mt < 2; mt++) {
                float p00 = 0.f, p01 = 0.f, p10 = 0.f, p11 = 0.f;
#pragma unroll
                for (int nt = 0; nt < 8; nt++) {
                    const int col = warp_n * 64 + nt * 8 + 2 * tig;
                    const float b0 = eb2s[col], b1 = eb2s[col + 1];
                    const float v0 = fmaxf(c[mt][nt][0] + b0, 0.f);
                    const float v1 = fmaxf(c[mt][nt][1] + b1, 0.f);
                    const float v2 = fmaxf(c[mt][nt][2] + b0, 0.f);
                    const float v3 = fmaxf(c[mt][nt][3] + b1, 0.f);
                    const float w00 = ew3s[col * 2],       w01 = ew3s[col * 2 + 1];
                    const float w10 = ew3s[(col + 1) * 2], w11 = ew3s[(col + 1) * 2 + 1];
                    p00 += v0 * w00 + v1 * w10;  p01 += v0 * w01 + v1 * w11;
                    p10 += v2 * w00 + v3 * w10;  p11 += v2 * w01 + v3 * w11;
                }
                const int r = warp_m * 32 + mt * 16 + grp;
                atomicAdd(&zcs[r * 2],           p00);
                atomicAdd(&zcs[r * 2 + 1],       p01);
                atomicAdd(&zcs[(r + 8) * 2],     p10);
                atomicAdd(&zcs[(r + 8) * 2 + 1], p11);
            }
            __syncthreads();

            if (tid < 128) {
                const long long row = row0 + tid;
                const float zc0 = zcs[tid * 2]     + eb3[e * 2];
                const float zc1 = zcs[tid * 2 + 1] + eb3[e * 2 + 1];
                *(float2*)(chart + ((long long)e * BB + row) * 2) = make_float2(zc0, zc1);
            }
            __syncthreads();   // zcs/ew3s/eb1s reuse next expert
        }
    }

    // ---------------- completion: 3rd finisher computes z ----------------
    __threadfence();
    __syncthreads();
    if (tid == 0) s_old = atomicAdd(&g_cnt[blockIdx.x], 1);
    __syncthreads();
    if (s_old == 2) {
        __threadfence();
        if (tid < 128) {
            const long long row = row0 + tid;
            float z0 = 0.f, z1 = 0.f;
#pragma unroll
            for (int e = 0; e < EE; e++) {
                const float w  = __ldcg(&wts[row * EE + e]);
                const float a0 = __ldcg(&chart[((long long)e * BB + row) * 2]);
                const float a1 = __ldcg(&chart[((long long)e * BB + row) * 2 + 1]);
                z0 += w * a0;
                z1 += w * a1;
            }
            *(float2*)(z + row * 2) = make_float2(z0, z1);
        }
    }
}

// ============================================================================
// Convert + pack to fp16. A-side: k-pairwise along rows. B-side (weights):
// transposed to [n][kp]. Resets g_cnt.
// ============================================================================
#define XN  (BB * (DD / 2))                 // 8388608
#define W1N (RH1 * (DD / 2))                // 65536
#define W2N (RH2 * (RH1 / 2))               // 16384
#define E1N (EE * HH * (DD / 2))            // 327680
#define E2N (EE * HH * (HH / 2))            // 81920
#define TOTN (XN + W1N + W2N + E1N + E2N)

__global__ __launch_bounds__(256) void cvt_all(
    const float2* __restrict__ x2, const float* __restrict__ rw1,
    const float* __restrict__ rw2, const float* __restrict__ ew1,
    const float* __restrict__ ew2,
    uint32_t* __restrict__ xtp, uint32_t* __restrict__ w1p,
    uint32_t* __restrict__ w2p, uint32_t* __restrict__ e1p,
    uint32_t* __restrict__ e2p)
{
    if (blockIdx.x == 0 && threadIdx.x < BB / 128) g_cnt[threadIdx.x] = 0;

    long long i = (long long)blockIdx.x * 256 + threadIdx.x;
    if (i < XN) { const float2 v = x2[i]; xtp[i] = pkh2(v.x, v.y); return; }
    i -= XN;
    if (i < W1N) {   // w1p[n][kp], n = i>>8? no: [n][kp] with kp dim 256
        const int n = (int)(i >> 8), kp = (int)(i & 255);
        w1p[i] = pkh2(rw1[(2 * kp) * RH1 + n], rw1[(2 * kp + 1) * RH1 + n]);
        return;
    }
    i -= W1N;
    if (i < W2N) {   // w2p[n][kp], kp dim 128
        const int n = (int)(i >> 7), kp = (int)(i & 127);
        w2p[i] = pkh2(rw2[(2 * kp) * RH2 + n], rw2[(2 * kp + 1) * RH2 + n]);
        return;
    }
    i -= W2N;
    if (i < E1N) {   // e1p[e][n][kp], kp dim 256
        const int e = (int)(i >> 15);
        const int n = (int)((i >> 8) & 127), kp = (int)(i & 255);
        e1p[i] = pkh2(ew1[(long long)e * DD * HH + (2 * kp) * HH + n],
                      ew1[(long long)e * DD * HH + (2 * kp + 1) * HH + n]);
        return;
    }
    i -= E1N;
    if (i < E2N) {   // e2p[e][n][kp], kp dim 64
        const int e = (int)(i >> 13);
        const int n = (int)((i >> 6) & 127), kp = (int)(i & 63);
        e2p[i] = pkh2(ew2[(long long)e * HH * HH + (2 * kp) * HH + n],
                      ew2[(long long)e * HH * HH + (2 * kp + 1) * HH + n]);
    }
}

// ============================================================================
extern "C" void kernel_launch(void* const* d_in, const int* in_sizes, int n_in,
                              void* d_out, int out_size)
{
    const float* x   = (const float*)d_in[0];
    const float* u   = (const float*)d_in[1];
    const float* rw1 = (const float*)d_in[2];
    const float* rb1 = (const float*)d_in[3];
    const float* rw2 = (const float*)d_in[4];
    const float* rb2 = (const float*)d_in[5];
    const float* rw3 = (const float*)d_in[6];
    const float* rb3 = (const float*)d_in[7];
    const float* ew1 = (const float*)d_in[8];
    const float* eb1 = (const float*)d_in[9];
    const float* ew2 = (const float*)d_in[10];
    const float* eb2 = (const float*)d_in[11];
    const float* ew3 = (const float*)d_in[12];
    const float* eb3 = (const float*)d_in[13];

    float* out   = (float*)d_out;
    float* z     = out;                                      // [B, 2]
    float* wts   = out + (size_t)BB * 2;                     // [B, E]
    float* chart = out + (size_t)BB * 2 + (size_t)BB * EE;   // [E, B, 2]

    uint32_t *xtp, *hr1p, *w1p, *w2p, *e1p, *e2p;
    cudaGetSymbolAddress((void**)&xtp, g_xtp);
    cudaGetSymbolAddress((void**)&hr1p, g_hr1p);
    cudaGetSymbolAddress((void**)&w1p, g_w1p);
    cudaGetSymbolAddress((void**)&w2p, g_w2p);
    cudaGetSymbolAddress((void**)&e1p, g_e1p);
    cudaGetSymbolAddress((void**)&e2p, g_e2p);

    cudaFuncSetAttribute(mega, cudaFuncAttributeMaxDynamicSharedMemorySize, MEGA_SMEM);

    cvt_all<<<(TOTN + 255) / 256, 256>>>(
        (const float2*)x, rw1, rw2, ew1, ew2, xtp, w1p, w2p, e1p, e2p);

    mega<<<dim3(BB / 128, 3), 256, MEGA_SMEM>>>(
        xtp, w1p, rb1, w2p, rb2, rw3, rb3, u,
        e1p, eb1, e2p, eb2, ew3, eb3, hr1p, wts, chart, z);
}